// round 12
// baseline (speedup 1.0000x reference)
#include <cuda_runtime.h>
#include <cstdint>

// Problem constants
#define BATCH 4
#define CH    256
#define NPIX  4096      // 64*64
#define C8    32
#define OCH   320       // 32(q) + 32(k) + 256(v)

#define LDS36 36        // smem row stride (floats)
#define ESHIFT 24.0f    // uniform logit shift (cancels in softmax ratio)

// ---------------- scratch (static device arrays; no allocation) ----------------
__device__ float g_W[OCH * CH];
__device__ float g_b[OCH];
__device__ float g_q[(size_t)BATCH * NPIX * C8];       // [b][n][d]
__device__ float g_k[(size_t)BATCH * NPIX * C8];       // [b][m][d]
// V in FRAGMENT-MAJOR layout: per b: [cb(16)][kb(512)][lane(32)][quad(4)]
__device__ float g_v[(size_t)BATCH * CH * NPIX];
__device__ float g_psum[(size_t)BATCH * 128 * NPIX];   // [b][slot][m] partial row sums

// ---------------- common PTX helpers -------------------------------------------
__device__ __forceinline__ void cp16(uint32_t dst, const float* src) {
    asm volatile("cp.async.cg.shared.global [%0], [%1], 16;\n" :: "r"(dst), "l"(src));
}
__device__ __forceinline__ void cp_commit() {
    asm volatile("cp.async.commit_group;\n" ::: "memory");
}
__device__ __forceinline__ void cp_wait0() {
    asm volatile("cp.async.wait_group 0;\n" ::: "memory");
}
__device__ __forceinline__ void cp_wait1() {
    asm volatile("cp.async.wait_group 1;\n" ::: "memory");
}

__device__ __forceinline__ void mma_tf32(float c[4], const uint32_t a[4],
                                         uint32_t b0, uint32_t b1) {
    asm volatile(
        "mma.sync.aligned.m16n8k8.row.col.f32.tf32.tf32.f32 "
        "{%0,%1,%2,%3}, {%4,%5,%6,%7}, {%8,%9}, {%0,%1,%2,%3};\n"
        : "+f"(c[0]), "+f"(c[1]), "+f"(c[2]), "+f"(c[3])
        : "r"(a[0]), "r"(a[1]), "r"(a[2]), "r"(a[3]), "r"(b0), "r"(b1));
}

__device__ __forceinline__ void split_tf32(float a, uint32_t& hi, uint32_t& lo) {
    uint32_t h;
    asm("cvt.rna.tf32.f32 %0, %1;" : "=r"(h) : "f"(a));
    float r = a - __uint_as_float(h);
    uint32_t l;
    asm("cvt.rna.tf32.f32 %0, %1;" : "=r"(l) : "f"(r));
    hi = h; lo = l;
}

// fragment-major index for V (within one batch)
__device__ __forceinline__ size_t vfrag_idx(int cc, int k) {
    int cb = cc >> 4, cl = cc & 15, kb = k >> 3, kl = k & 7;
    int lane = ((cl & 7) << 2) + (kl & 3);
    int q = ((kl >= 4) ? 2 : 0) + ((cl >= 8) ? 1 : 0);
    return ((size_t)(cb * 512 + kb) * 32 + lane) * 4 + q;
}

// ---------------- kernel 0: pack weights/bias ----------------------------------
__global__ void pack_w(const float* __restrict__ Wq, const float* __restrict__ bq,
                       const float* __restrict__ Wk, const float* __restrict__ bk,
                       const float* __restrict__ Wv, const float* __restrict__ bv) {
    int i = blockIdx.x * 256 + threadIdx.x;
    if (i < 32 * 256)       g_W[i] = Wq[i];
    else if (i < 64 * 256)  g_W[i] = Wk[i - 32 * 256];
    else                    g_W[i] = Wv[i - 64 * 256];
    if (i < 32)             g_b[i] = bq[i];
    else if (i < 64)        g_b[i] = bk[i - 32];
    else if (i < 320)       g_b[i] = bv[i - 64];
}

// ---------------- kernel 1: fused q/k/v projection (split-tf32 MMA) ------------
__global__ void __launch_bounds__(256)
proj_gemm_tc(const float* __restrict__ x) {
    __shared__ float Ws[64 * LDS36];
    __shared__ float Xs[128 * LDS36];
    const int b = blockIdx.z;
    const int och0 = blockIdx.y * 64;
    const int n0 = blockIdx.x * 128;
    const float* xb = x + (size_t)b * CH * NPIX;
    const int tid = threadIdx.x;
    const int lane = tid & 31, w = tid >> 5;
    const int wmo = w >> 2, wn = w & 3;
    const int lr = lane >> 2, lm = lane & 3;

    const uint32_t wsb = (uint32_t)__cvta_generic_to_shared(Ws);
    const int lrow = tid >> 3;
    const int lkq = (tid & 7) << 2;

    float acc[2][4][4] = {};

    for (int c0 = 0; c0 < CH; c0 += 32) {
#pragma unroll
        for (int j = 0; j < 2; j++) {
            int r = lrow + 32 * j;
            cp16(wsb + (r * LDS36 + lkq) * 4, g_W + (size_t)(och0 + r) * CH + c0 + lkq);
        }
        cp_commit();
        {
            int cc = tid >> 3;
#pragma unroll
            for (int j = 0; j < 4; j++) {
                int nn4 = (tid & 7) + 8 * j;
                const float4 v4 = *(const float4*)(xb + (size_t)(c0 + cc) * NPIX + n0 + nn4 * 4);
                float* dst = Xs + (nn4 * 4) * LDS36 + cc;
                dst[0 * LDS36] = v4.x;
                dst[1 * LDS36] = v4.y;
                dst[2 * LDS36] = v4.z;
                dst[3 * LDS36] = v4.w;
            }
        }
        cp_wait0();
        __syncthreads();

#pragma unroll
        for (int kc = 0; kc < 4; kc++) {
            uint32_t ah[2][4], al[2][4];
#pragma unroll
            for (int ct = 0; ct < 2; ct++) {
                const float* p = Ws + (wmo * 32 + ct * 16 + lr) * LDS36 + kc * 8 + lm;
                split_tf32(p[0],             ah[ct][0], al[ct][0]);
                split_tf32(p[8 * LDS36],     ah[ct][1], al[ct][1]);
                split_tf32(p[4],             ah[ct][2], al[ct][2]);
                split_tf32(p[8 * LDS36 + 4], ah[ct][3], al[ct][3]);
            }
            uint32_t bh[4][2], bl[4][2];
#pragma unroll
            for (int nt = 0; nt < 4; nt++) {
                const float* p = Xs + (wn * 32 + nt * 8 + lr) * LDS36 + kc * 8 + lm;
                split_tf32(p[0], bh[nt][0], bl[nt][0]);
                split_tf32(p[4], bh[nt][1], bl[nt][1]);
            }
#pragma unroll
            for (int ct = 0; ct < 2; ct++)
#pragma unroll
                for (int nt = 0; nt < 4; nt++) {
                    mma_tf32(acc[ct][nt], ah[ct], bl[nt][0], bl[nt][1]);
                    mma_tf32(acc[ct][nt], al[ct], bh[nt][0], bh[nt][1]);
                    mma_tf32(acc[ct][nt], ah[ct], bh[nt][0], bh[nt][1]);
                }
        }
        __syncthreads();
    }

    float* vb = g_v + ((size_t)b << 20);
#pragma unroll
    for (int ct = 0; ct < 2; ct++) {
#pragma unroll
        for (int h = 0; h < 2; h++) {
            int och = och0 + wmo * 32 + ct * 16 + lr + h * 8;
            float bias = g_b[och];
#pragma unroll
            for (int nt = 0; nt < 4; nt++) {
                int n = n0 + wn * 32 + nt * 8 + lm * 2;
                float v0 = acc[ct][nt][h * 2 + 0] + bias;
                float v1 = acc[ct][nt][h * 2 + 1] + bias;
                if (och < 32) {
                    g_q[(((size_t)b << 12) + n) * C8 + och] = v0;
                    g_q[(((size_t)b << 12) + n + 1) * C8 + och] = v1;
                } else if (och < 64) {
                    g_k[(((size_t)b << 12) + n) * C8 + (och - 32)] = v0;
                    g_k[(((size_t)b << 12) + n + 1) * C8 + (och - 32)] = v1;
                } else {
                    int cc = och - 64;
                    vb[vfrag_idx(cc, n)]     = v0;
                    vb[vfrag_idx(cc, n + 1)] = v1;
                }
            }
        }
    }
}

// ---------------- kernel 2: e = exp(logits - SHIFT) -> att + partial row sums --
__global__ void __launch_bounds__(256)
s_gemm_e(float* __restrict__ att) {
    __shared__ float Ks[128 * LDS36];
    __shared__ float Qs[128 * LDS36];
    const int b = blockIdx.z;
    const int m0 = blockIdx.y * 128;
    const int n0 = blockIdx.x * 128;
    const int tid = threadIdx.x;
    const int lane = tid & 31, w = tid >> 5;
    const int wc = w >> 2, wm = w & 3;
    const int lr = lane >> 2, lm = lane & 3;

    const uint32_t ksb = (uint32_t)__cvta_generic_to_shared(Ks);
    const uint32_t qsb = (uint32_t)__cvta_generic_to_shared(Qs);
    const int lrow = tid >> 3;
    const int lkq = (tid & 7) << 2;

    const float* kbase = g_k + (((size_t)b << 12) + m0) * C8;
    const float* qbase = g_q + (((size_t)b << 12) + n0) * C8;
#pragma unroll
    for (int j = 0; j < 4; j++) {
        int r = lrow + 32 * j;
        cp16(ksb + (r * LDS36 + lkq) * 4, kbase + (size_t)r * C8 + lkq);
        cp16(qsb + (r * LDS36 + lkq) * 4, qbase + (size_t)r * C8 + lkq);
    }
    cp_commit();
    cp_wait0();
    __syncthreads();

    float acc[4][4][4] = {};
#pragma unroll
    for (int kc = 0; kc < 4; kc++) {
        uint32_t ah[4][4], al[4][4];
#pragma unroll
        for (int ct = 0; ct < 4; ct++) {
            const float* p = Ks + (wc * 64 + ct * 16 + lr) * LDS36 + kc * 8 + lm;
            split_tf32(p[0],             ah[ct][0], al[ct][0]);
            split_tf32(p[8 * LDS36],     ah[ct][1], al[ct][1]);
            split_tf32(p[4],             ah[ct][2], al[ct][2]);
            split_tf32(p[8 * LDS36 + 4], ah[ct][3], al[ct][3]);
        }
        uint32_t bh[4][2], bl[4][2];
#pragma unroll
        for (int nt = 0; nt < 4; nt++) {
            const float* p = Qs + (wm * 32 + nt * 8 + lr) * LDS36 + kc * 8 + lm;
            split_tf32(p[0], bh[nt][0], bl[nt][0]);
            split_tf32(p[4], bh[nt][1], bl[nt][1]);
        }
#pragma unroll
        for (int ct = 0; ct < 4; ct++)
#pragma unroll
            for (int nt = 0; nt < 4; nt++) {
                mma_tf32(acc[ct][nt], ah[ct], bl[nt][0], bl[nt][1]);
                mma_tf32(acc[ct][nt], al[ct], bh[nt][0], bh[nt][1]);
                mma_tf32(acc[ct][nt], ah[ct], bh[nt][0], bh[nt][1]);
            }
    }

    float* ab = att + ((size_t)b << 24);
    const int slot = ((n0 >> 7) << 2) + wm;
#pragma unroll
    for (int ct = 0; ct < 4; ct++) {
#pragma unroll
        for (int h = 0; h < 2; h++) {
            int m = m0 + wc * 64 + ct * 16 + lr + h * 8;
            float rsum = 0.f;
#pragma unroll
            for (int nt = 0; nt < 4; nt++) {
                int n = n0 + wm * 32 + nt * 8 + lm * 2;
                float e0 = __expf(acc[ct][nt][h * 2 + 0] - ESHIFT);
                float e1 = __expf(acc[ct][nt][h * 2 + 1] - ESHIFT);
                rsum += e0 + e1;
                *(float2*)(ab + (size_t)m * NPIX + n) = make_float2(e0, e1);
            }
            rsum += __shfl_xor_sync(0xffffffffu, rsum, 1);
            rsum += __shfl_xor_sync(0xffffffffu, rsum, 2);
            if (lm == 0)
                g_psum[((size_t)b * 128 + slot) * NPIX + m] = rsum;
        }
    }
}

// ---------------- kernel 3: O = V*e^T*inv + normalize att in place --------------
// CTA 256c x 64m, 256 threads, 2 CTAs/SM, K chunk 32, 2-stage cp.async.
// A (V) smem: linear fragment-major 8192 floats/stage (one LDS.128 per fragment).
// B (e) smem: row-major 64 x LDS36.
#define A_STG 8192                 // floats per A stage
#define B_STG (64 * LDS36)         // 2304 floats per B stage
#define B_BASE (2 * A_STG)         // B region after 2 A stages

extern __shared__ float o5_smem[];

__global__ void __launch_bounds__(256, 2)
o_gemm5(const float* __restrict__ x, const float* __restrict__ gamma,
        float* __restrict__ att, float* __restrict__ out) {
    const int b  = blockIdx.z;
    const int m0 = blockIdx.x * 64;
    const int tid = threadIdx.x;
    const int lane = tid & 31, w = tid >> 5;
    const int wc = w >> 1, wm = w & 1;     // c quarter (64 rows), m half (32 cols)
    const int lr = lane >> 2, lm = lane & 3;

    const float* __restrict__ vbase = g_v + ((size_t)b << 20);
    float* abase = att + ((size_t)b << 24) + ((size_t)m0 << 12);

    const uint32_t sbase = (uint32_t)__cvta_generic_to_shared(o5_smem);

    __shared__ float part_s[4][64];
    __shared__ float inv_s[64];

    auto issue_tile = [&](int it) {
        const int s = it & 1;
        const int kb0 = it << 2;           // 4 k-blocks (of 8) per chunk
        uint32_t dA = sbase + (s * A_STG) * 4;
        uint32_t dB = sbase + (B_BASE + s * B_STG) * 4;
        // A: 2048 chunks of 16B, fragment-major linear
#pragma unroll
        for (int j = 0; j < 8; j++) {
            int ci = tid + j * 256;
            int cb = ci >> 7, rest = ci & 127;   // kb_l = rest>>5, ln = rest&31
            const float* src = vbase
                + ((size_t)(cb * 512 + kb0 + (rest >> 5)) * 32 + (rest & 31)) * 4;
            cp16(dA + ci * 16, src);
        }
        // B: 512 chunks of 16B, row-major padded
#pragma unroll
        for (int j = 0; j < 2; j++) {
            int ci = tid * 2 + j;               // 0..511
            int r = ci >> 3, kq = ci & 7;
            cp16(dB + (r * LDS36 + kq * 4) * 4,
                 abase + (size_t)r * NPIX + (it << 5) + kq * 4);
        }
        cp_commit();
    };

    issue_tile(0);
    issue_tile(1);

    // deterministic row-sum inverse: 128 psum slots per row
    {
        int p = tid >> 6, ml = tid & 63;
        const float* pp = g_psum + ((size_t)b * 128 + p * 32) * NPIX + m0 + ml;
        float s = 0.f;
#pragma unroll 8
        for (int j = 0; j < 32; j++) s += pp[(size_t)j * NPIX];
        part_s[p][ml] = s;
    }
    __syncthreads();
    if (tid < 64)
        inv_s[tid] = 1.0f / (part_s[0][tid] + part_s[1][tid] + part_s[2][tid] + part_s[3][tid]);

    float acc[4][4][4] = {};
    const int NITER = NPIX / 32;           // 128
    for (int it = 0; it < NITER; it++) {
        const int s = it & 1;
        if (it < NITER - 1) cp_wait1();
        else                cp_wait0();
        __syncthreads();                   // publishes inv_s on it==0

        const float* bA = o5_smem + s * A_STG;
        const float* bB = o5_smem + B_BASE + s * B_STG;

        // normalized att writeback for this tile (e * inv[m])
        {
            int r  = tid >> 2;             // 0..63
            int s0 = (tid & 3) << 1;       // float4 slots {s0, s0+1}
            float iv = inv_s[r];
            const float* src = bB + r * LDS36;
            float* dst = abase + (size_t)r * NPIX + (it << 5);
#pragma unroll
            for (int ss = 0; ss < 2; ss++) {
                const float* p = src + (s0 + ss) * 4;
                float4 vv = make_float4(p[0] * iv, p[1] * iv, p[2] * iv, p[3] * iv);
                *(float4*)(dst + (s0 + ss) * 4) = vv;
            }
        }

#pragma unroll
        for (int kc = 0; kc < 4; kc++) {
            uint32_t af[4][4];
#pragma unroll
            for (int ct = 0; ct < 4; ct++) {
                int cb_l = wc * 4 + ct;
                const uint4 q4 = *(const uint4*)(bA + ((cb_l * 4 + kc) * 32 + lane) * 4);
                af[ct][0] = q4.x; af[ct][1] = q4.y; af[ct][2] = q4.z; af[ct][3] = q4.w;
            }
            uint32_t bf[4][2];
#pragma unroll
            for (int nt = 0; nt < 4; nt++) {
                const float* p = bB + (wm * 32 + nt * 8 + lr) * LDS36 + kc * 8 + lm;
                bf[nt][0] = __float_as_uint(p[0]);
                bf[nt][1] = __float_as_uint(p[4]);
            }
#pragma unroll
            for (int ct = 0; ct < 4; ct++)
#pragma unroll
                for (int nt = 0; nt < 4; nt++)
                    mma_tf32(acc[ct][nt], af[ct], bf[nt][0], bf[nt][1]);
        }
        __syncthreads();
        if (it + 2 < NITER) issue_tile(it + 2);
    }

    const float g = __ldg(gamma);
    const float* xb = x + ((size_t)b << 20);
    float* ob = out + ((size_t)b << 20);
#pragma unroll
    for (int ct = 0; ct < 4; ct++) {
#pragma unroll
        for (int h = 0; h < 2; h++) {
            int c = wc * 64 + ct * 16 + lr + h * 8;
            size_t base = ((size_t)c << 12) + m0;
#pragma unroll
            for (int nt = 0; nt < 4; nt++) {
                int ml = wm * 32 + nt * 8 + lm * 2;
                float2 xv = *(const float2*)(xb + base + ml);
                float s0 = acc[ct][nt][h * 2 + 0] * inv_s[ml];
                float s1 = acc[ct][nt][h * 2 + 1] * inv_s[ml + 1];
                float2 st = make_float2(fmaf(g, s0, xv.x), fmaf(g, s1, xv.y));
                *(float2*)(ob + base + ml) = st;
            }
        }
    }
}

// ---------------- launch --------------------------------------------------------
extern "C" void kernel_launch(void* const* d_in, const int* in_sizes, int n_in,
                              void* d_out, int out_size) {
    const float* x     = (const float*)d_in[0];
    const float* Wq    = (const float*)d_in[1];
    const float* bq    = (const float*)d_in[2];
    const float* Wk    = (const float*)d_in[3];
    const float* bk    = (const float*)d_in[4];
    const float* Wv    = (const float*)d_in[5];
    const float* bv    = (const float*)d_in[6];
    const float* gamma = (const float*)d_in[7];

    float* out = (float*)d_out;
    float* att = out + (size_t)BATCH * CH * NPIX;

    static const size_t O5_SMEM_BYTES = (size_t)(2 * A_STG + 2 * B_STG) * sizeof(float);
    cudaFuncSetAttribute(o_gemm5, cudaFuncAttributeMaxDynamicSharedMemorySize,
                         (int)O5_SMEM_BYTES);   // 83,968 B -> 2 CTAs/SM

    pack_w<<<320, 256>>>(Wq, bq, Wk, bk, Wv, bv);
    proj_gemm_tc<<<dim3(NPIX / 128, OCH / 64, BATCH), 256>>>(x);
    s_gemm_e<<<dim3(NPIX / 128, NPIX / 128, BATCH), 256>>>(att);
    o_gemm5<<<dim3(NPIX / 64, 1, BATCH), 256, O5_SMEM_BYTES>>>(x, gamma, att, out);
}

// round 17
// speedup vs baseline: 1.0574x; 1.0574x over previous
#include <cuda_runtime.h>
#include <cstdint>

// Problem constants
#define BATCH 4
#define CH    256
#define NPIX  4096      // 64*64
#define C8    32
#define OCH   320       // 32(q) + 32(k) + 256(v)

#define LDS36 36        // smem row stride (floats)
#define ESHIFT 24.0f    // uniform logit shift (cancels in softmax ratio)

// ---------------- scratch (static device arrays; no allocation) ----------------
__device__ float g_W[OCH * CH];
__device__ float g_b[OCH];
__device__ float g_q[(size_t)BATCH * NPIX * C8];       // [b][n][d]
__device__ float g_k[(size_t)BATCH * NPIX * C8];       // [b][m][d]
// V in FRAGMENT-MAJOR layout: per b: [cb(16)][kb(512)][lane(32)][quad(4)]
__device__ float g_v[(size_t)BATCH * CH * NPIX];
__device__ float g_psum[(size_t)BATCH * 128 * NPIX];   // [b][slot][m] partial row sums

// ---------------- common PTX helpers -------------------------------------------
__device__ __forceinline__ void cp16(uint32_t dst, const float* src) {
    asm volatile("cp.async.cg.shared.global [%0], [%1], 16;\n" :: "r"(dst), "l"(src));
}
__device__ __forceinline__ void cp_commit() {
    asm volatile("cp.async.commit_group;\n" ::: "memory");
}
__device__ __forceinline__ void cp_wait0() {
    asm volatile("cp.async.wait_group 0;\n" ::: "memory");
}
__device__ __forceinline__ void cp_wait1() {
    asm volatile("cp.async.wait_group 1;\n" ::: "memory");
}
__device__ __forceinline__ void cp_wait2() {
    asm volatile("cp.async.wait_group 2;\n" ::: "memory");
}

__device__ __forceinline__ void mma_tf32(float c[4], const uint32_t a[4],
                                         uint32_t b0, uint32_t b1) {
    asm volatile(
        "mma.sync.aligned.m16n8k8.row.col.f32.tf32.tf32.f32 "
        "{%0,%1,%2,%3}, {%4,%5,%6,%7}, {%8,%9}, {%0,%1,%2,%3};\n"
        : "+f"(c[0]), "+f"(c[1]), "+f"(c[2]), "+f"(c[3])
        : "r"(a[0]), "r"(a[1]), "r"(a[2]), "r"(a[3]), "r"(b0), "r"(b1));
}

__device__ __forceinline__ void split_tf32(float a, uint32_t& hi, uint32_t& lo) {
    uint32_t h;
    asm("cvt.rna.tf32.f32 %0, %1;" : "=r"(h) : "f"(a));
    float r = a - __uint_as_float(h);
    uint32_t l;
    asm("cvt.rna.tf32.f32 %0, %1;" : "=r"(l) : "f"(r));
    hi = h; lo = l;
}

// fragment-major index for V (within one batch)
__device__ __forceinline__ size_t vfrag_idx(int cc, int k) {
    int cb = cc >> 4, cl = cc & 15, kb = k >> 3, kl = k & 7;
    int lane = ((cl & 7) << 2) + (kl & 3);
    int q = ((kl >= 4) ? 2 : 0) + ((cl >= 8) ? 1 : 0);
    return ((size_t)(cb * 512 + kb) * 32 + lane) * 4 + q;
}

// ---------------- kernel 0: pack weights/bias ----------------------------------
__global__ void pack_w(const float* __restrict__ Wq, const float* __restrict__ bq,
                       const float* __restrict__ Wk, const float* __restrict__ bk,
                       const float* __restrict__ Wv, const float* __restrict__ bv) {
    int i = blockIdx.x * 256 + threadIdx.x;
    if (i < 32 * 256)       g_W[i] = Wq[i];
    else if (i < 64 * 256)  g_W[i] = Wk[i - 32 * 256];
    else                    g_W[i] = Wv[i - 64 * 256];
    if (i < 32)             g_b[i] = bq[i];
    else if (i < 64)        g_b[i] = bk[i - 32];
    else if (i < 320)       g_b[i] = bv[i - 64];
}

// ---------------- kernel 1: fused q/k/v projection (split-tf32 MMA) ------------
__global__ void __launch_bounds__(256)
proj_gemm_tc(const float* __restrict__ x) {
    __shared__ float Ws[64 * LDS36];
    __shared__ float Xs[128 * LDS36];
    const int b = blockIdx.z;
    const int och0 = blockIdx.y * 64;
    const int n0 = blockIdx.x * 128;
    const float* xb = x + (size_t)b * CH * NPIX;
    const int tid = threadIdx.x;
    const int lane = tid & 31, w = tid >> 5;
    const int wmo = w >> 2, wn = w & 3;
    const int lr = lane >> 2, lm = lane & 3;

    const uint32_t wsb = (uint32_t)__cvta_generic_to_shared(Ws);
    const int lrow = tid >> 3;
    const int lkq = (tid & 7) << 2;

    float acc[2][4][4] = {};

    for (int c0 = 0; c0 < CH; c0 += 32) {
#pragma unroll
        for (int j = 0; j < 2; j++) {
            int r = lrow + 32 * j;
            cp16(wsb + (r * LDS36 + lkq) * 4, g_W + (size_t)(och0 + r) * CH + c0 + lkq);
        }
        cp_commit();
        {
            int cc = tid >> 3;
#pragma unroll
            for (int j = 0; j < 4; j++) {
                int nn4 = (tid & 7) + 8 * j;
                const float4 v4 = *(const float4*)(xb + (size_t)(c0 + cc) * NPIX + n0 + nn4 * 4);
                float* dst = Xs + (nn4 * 4) * LDS36 + cc;
                dst[0 * LDS36] = v4.x;
                dst[1 * LDS36] = v4.y;
                dst[2 * LDS36] = v4.z;
                dst[3 * LDS36] = v4.w;
            }
        }
        cp_wait0();
        __syncthreads();

#pragma unroll
        for (int kc = 0; kc < 4; kc++) {
            uint32_t ah[2][4], al[2][4];
#pragma unroll
            for (int ct = 0; ct < 2; ct++) {
                const float* p = Ws + (wmo * 32 + ct * 16 + lr) * LDS36 + kc * 8 + lm;
                split_tf32(p[0],             ah[ct][0], al[ct][0]);
                split_tf32(p[8 * LDS36],     ah[ct][1], al[ct][1]);
                split_tf32(p[4],             ah[ct][2], al[ct][2]);
                split_tf32(p[8 * LDS36 + 4], ah[ct][3], al[ct][3]);
            }
            uint32_t bh[4][2], bl[4][2];
#pragma unroll
            for (int nt = 0; nt < 4; nt++) {
                const float* p = Xs + (wn * 32 + nt * 8 + lr) * LDS36 + kc * 8 + lm;
                split_tf32(p[0], bh[nt][0], bl[nt][0]);
                split_tf32(p[4], bh[nt][1], bl[nt][1]);
            }
#pragma unroll
            for (int ct = 0; ct < 2; ct++)
#pragma unroll
                for (int nt = 0; nt < 4; nt++) {
                    mma_tf32(acc[ct][nt], ah[ct], bl[nt][0], bl[nt][1]);
                    mma_tf32(acc[ct][nt], al[ct], bh[nt][0], bh[nt][1]);
                    mma_tf32(acc[ct][nt], ah[ct], bh[nt][0], bh[nt][1]);
                }
        }
        __syncthreads();
    }

    float* vb = g_v + ((size_t)b << 20);
#pragma unroll
    for (int ct = 0; ct < 2; ct++) {
#pragma unroll
        for (int h = 0; h < 2; h++) {
            int och = och0 + wmo * 32 + ct * 16 + lr + h * 8;
            float bias = g_b[och];
#pragma unroll
            for (int nt = 0; nt < 4; nt++) {
                int n = n0 + wn * 32 + nt * 8 + lm * 2;
                float v0 = acc[ct][nt][h * 2 + 0] + bias;
                float v1 = acc[ct][nt][h * 2 + 1] + bias;
                if (och < 32) {
                    g_q[(((size_t)b << 12) + n) * C8 + och] = v0;
                    g_q[(((size_t)b << 12) + n + 1) * C8 + och] = v1;
                } else if (och < 64) {
                    g_k[(((size_t)b << 12) + n) * C8 + (och - 32)] = v0;
                    g_k[(((size_t)b << 12) + n + 1) * C8 + (och - 32)] = v1;
                } else {
                    int cc = och - 64;
                    vb[vfrag_idx(cc, n)]     = v0;
                    vb[vfrag_idx(cc, n + 1)] = v1;
                }
            }
        }
    }
}

// ---------------- kernel 2: e = exp(logits - SHIFT) -> att + partial row sums --
__global__ void __launch_bounds__(256)
s_gemm_e(float* __restrict__ att) {
    __shared__ float Ks[128 * LDS36];
    __shared__ float Qs[128 * LDS36];
    const int b = blockIdx.z;
    const int m0 = blockIdx.y * 128;
    const int n0 = blockIdx.x * 128;
    const int tid = threadIdx.x;
    const int lane = tid & 31, w = tid >> 5;
    const int wc = w >> 2, wm = w & 3;
    const int lr = lane >> 2, lm = lane & 3;

    const uint32_t ksb = (uint32_t)__cvta_generic_to_shared(Ks);
    const uint32_t qsb = (uint32_t)__cvta_generic_to_shared(Qs);
    const int lrow = tid >> 3;
    const int lkq = (tid & 7) << 2;

    const float* kbase = g_k + (((size_t)b << 12) + m0) * C8;
    const float* qbase = g_q + (((size_t)b << 12) + n0) * C8;
#pragma unroll
    for (int j = 0; j < 4; j++) {
        int r = lrow + 32 * j;
        cp16(ksb + (r * LDS36 + lkq) * 4, kbase + (size_t)r * C8 + lkq);
        cp16(qsb + (r * LDS36 + lkq) * 4, qbase + (size_t)r * C8 + lkq);
    }
    cp_commit();
    cp_wait0();
    __syncthreads();

    float acc[4][4][4] = {};
#pragma unroll
    for (int kc = 0; kc < 4; kc++) {
        uint32_t ah[4][4], al[4][4];
#pragma unroll
        for (int ct = 0; ct < 4; ct++) {
            const float* p = Ks + (wc * 64 + ct * 16 + lr) * LDS36 + kc * 8 + lm;
            split_tf32(p[0],             ah[ct][0], al[ct][0]);
            split_tf32(p[8 * LDS36],     ah[ct][1], al[ct][1]);
            split_tf32(p[4],             ah[ct][2], al[ct][2]);
            split_tf32(p[8 * LDS36 + 4], ah[ct][3], al[ct][3]);
        }
        uint32_t bh[4][2], bl[4][2];
#pragma unroll
        for (int nt = 0; nt < 4; nt++) {
            const float* p = Qs + (wm * 32 + nt * 8 + lr) * LDS36 + kc * 8 + lm;
            split_tf32(p[0], bh[nt][0], bl[nt][0]);
            split_tf32(p[4], bh[nt][1], bl[nt][1]);
        }
#pragma unroll
        for (int ct = 0; ct < 4; ct++)
#pragma unroll
            for (int nt = 0; nt < 4; nt++) {
                mma_tf32(acc[ct][nt], ah[ct], bl[nt][0], bl[nt][1]);
                mma_tf32(acc[ct][nt], al[ct], bh[nt][0], bh[nt][1]);
                mma_tf32(acc[ct][nt], ah[ct], bh[nt][0], bh[nt][1]);
            }
    }

    float* ab = att + ((size_t)b << 24);
    const int slot = ((n0 >> 7) << 2) + wm;
#pragma unroll
    for (int ct = 0; ct < 4; ct++) {
#pragma unroll
        for (int h = 0; h < 2; h++) {
            int m = m0 + wc * 64 + ct * 16 + lr + h * 8;
            float rsum = 0.f;
#pragma unroll
            for (int nt = 0; nt < 4; nt++) {
                int n = n0 + wm * 32 + nt * 8 + lm * 2;
                float e0 = __expf(acc[ct][nt][h * 2 + 0] - ESHIFT);
                float e1 = __expf(acc[ct][nt][h * 2 + 1] - ESHIFT);
                rsum += e0 + e1;
                *(float2*)(ab + (size_t)m * NPIX + n) = make_float2(e0, e1);
            }
            rsum += __shfl_xor_sync(0xffffffffu, rsum, 1);
            rsum += __shfl_xor_sync(0xffffffffu, rsum, 2);
            if (lm == 0)
                g_psum[((size_t)b * 128 + slot) * NPIX + m] = rsum;
        }
    }
}

// ---------------- kernel 3: O = V*e^T*inv + normalize att in place --------------
// CTA 256c x 128m, 512 threads, K chunk 32, 4-stage ring, ONE barrier per iter.
// A (V) smem: linear fragment-major 8192 floats/stage; B (e): 128 x LDS36.
#define A_STG 8192                  // floats per A stage
#define B_STG (128 * LDS36)         // 4608 floats per B stage
#define STG_F (A_STG + B_STG)       // 12800 floats per stage

extern __shared__ float o6_smem[];

__global__ void __launch_bounds__(512, 1)
o_gemm6(const float* __restrict__ x, const float* __restrict__ gamma,
        float* __restrict__ att, float* __restrict__ out) {
    const int b  = blockIdx.z;
    const int m0 = blockIdx.x * 128;
    const int tid = threadIdx.x;
    const int lane = tid & 31, w = tid >> 5;
    const int wc = w >> 2, wm = w & 3;     // c quarter (64 rows), m quarter (32 cols)
    const int lr = lane >> 2, lm = lane & 3;

    const float* __restrict__ vbase = g_v + ((size_t)b << 20);
    float* abase = att + ((size_t)b << 24) + ((size_t)m0 << 12);

    const uint32_t sbase = (uint32_t)__cvta_generic_to_shared(o6_smem);

    __shared__ float part_s[4][128];
    __shared__ float inv_s[128];

    auto issue_tile = [&](int it) {
        const int s = it & 3;
        const int kb0 = it << 2;            // 4 k-blocks (of 8) per chunk
        uint32_t dA = sbase + (s * STG_F) * 4;
        uint32_t dB = dA + A_STG * 4;
        // A: 2048 chunks of 16B, fragment-major linear
#pragma unroll
        for (int j = 0; j < 4; j++) {
            int ci = tid + j * 512;
            int cb = ci >> 7, rest = ci & 127;   // kb_l = rest>>5, ln = rest&31
            const float* src = vbase
                + ((size_t)(cb * 512 + kb0 + (rest >> 5)) * 32 + (rest & 31)) * 4;
            cp16(dA + ci * 16, src);
        }
        // B: 1024 chunks of 16B, row-major padded
#pragma unroll
        for (int j = 0; j < 2; j++) {
            int ci = tid * 2 + j;               // 0..1023
            int r = ci >> 3, kq = ci & 7;
            cp16(dB + (r * LDS36 + kq * 4) * 4,
                 abase + (size_t)r * NPIX + (it << 5) + kq * 4);
        }
        cp_commit();
    };

    issue_tile(0);
    issue_tile(1);
    issue_tile(2);

    // deterministic row-sum inverse: 128 psum slots per row
    {
        int p = tid >> 7, ml = tid & 127;
        const float* pp = g_psum + ((size_t)b * 128 + p * 32) * NPIX + m0 + ml;
        float s = 0.f;
#pragma unroll 8
        for (int j = 0; j < 32; j++) s += pp[(size_t)j * NPIX];
        part_s[p][ml] = s;
    }
    __syncthreads();
    if (tid < 128)
        inv_s[tid] = 1.0f / (part_s[0][tid] + part_s[1][tid] + part_s[2][tid] + part_s[3][tid]);
    __syncthreads();

    // hoisted writeback constants
    const int wb_r  = tid >> 2;             // 0..127
    const int wb_s0 = (tid & 3) << 1;       // float4 slots {s0, s0+1}
    const float wb_iv = inv_s[wb_r];
    float* const wb_dst0 = abase + (size_t)wb_r * NPIX;

    float acc[4][4][4] = {};
    const int NITER = NPIX / 32;            // 128
    for (int it = 0; it < NITER; it++) {
        const int s = it & 3;
        // groups issued through min(it+2,127); need group `it` complete
        if (it < 126)       cp_wait2();
        else if (it == 126) cp_wait1();
        else                cp_wait0();
        __syncthreads();                    // single barrier per iteration

        // refill the slot freed at iteration it-1 (slot (it+3)&3 == (it-1)&3)
        if (it + 3 < NITER) issue_tile(it + 3);

        const float* bA = o6_smem + s * STG_F;
        const float* bB = bA + A_STG;

        // normalized att writeback for this tile (e * inv[m])
        {
            const float* src = bB + wb_r * LDS36;
            float* dst = wb_dst0 + (it << 5);
#pragma unroll
            for (int ss = 0; ss < 2; ss++) {
                const float* p = src + (wb_s0 + ss) * 4;
                float4 vv = make_float4(p[0] * wb_iv, p[1] * wb_iv,
                                        p[2] * wb_iv, p[3] * wb_iv);
                *(float4*)(dst + (wb_s0 + ss) * 4) = vv;
            }
        }

#pragma unroll
        for (int kc = 0; kc < 4; kc++) {
            uint32_t af[4][4];
#pragma unroll
            for (int ct = 0; ct < 4; ct++) {
                int cb_l = wc * 4 + ct;
                const uint4 q4 = *(const uint4*)(bA + ((cb_l * 4 + kc) * 32 + lane) * 4);
                af[ct][0] = q4.x; af[ct][1] = q4.y; af[ct][2] = q4.z; af[ct][3] = q4.w;
            }
            uint32_t bf[4][2];
#pragma unroll
            for (int nt = 0; nt < 4; nt++) {
                const float* p = bB + (wm * 32 + nt * 8 + lr) * LDS36 + kc * 8 + lm;
                bf[nt][0] = __float_as_uint(p[0]);
                bf[nt][1] = __float_as_uint(p[4]);
            }
#pragma unroll
            for (int ct = 0; ct < 4; ct++)
#pragma unroll
                for (int nt = 0; nt < 4; nt++)
                    mma_tf32(acc[ct][nt], af[ct], bf[nt][0], bf[nt][1]);
        }
        // no second barrier: the next iteration's refill targets a different slot,
        // and the top-of-loop barrier orders reads-before-overwrite.
    }

    const float g = __ldg(gamma);
    const float* xb = x + ((size_t)b << 20);
    float* ob = out + ((size_t)b << 20);
#pragma unroll
    for (int ct = 0; ct < 4; ct++) {
#pragma unroll
        for (int h = 0; h < 2; h++) {
            int c = wc * 64 + ct * 16 + lr + h * 8;
            size_t base = ((size_t)c << 12) + m0;
#pragma unroll
            for (int nt = 0; nt < 4; nt++) {
                int ml = wm * 32 + nt * 8 + lm * 2;
                float2 xv = *(const float2*)(xb + base + ml);
                float s0 = acc[ct][nt][h * 2 + 0] * inv_s[ml];
                float s1 = acc[ct][nt][h * 2 + 1] * inv_s[ml + 1];
                float2 st = make_float2(fmaf(g, s0, xv.x), fmaf(g, s1, xv.y));
                *(float2*)(ob + base + ml) = st;
            }
        }
    }
}

// ---------------- launch --------------------------------------------------------
extern "C" void kernel_launch(void* const* d_in, const int* in_sizes, int n_in,
                              void* d_out, int out_size) {
    const float* x     = (const float*)d_in[0];
    const float* Wq    = (const float*)d_in[1];
    const float* bq    = (const float*)d_in[2];
    const float* Wk    = (const float*)d_in[3];
    const float* bk    = (const float*)d_in[4];
    const float* Wv    = (const float*)d_in[5];
    const float* bv    = (const float*)d_in[6];
    const float* gamma = (const float*)d_in[7];

    float* out = (float*)d_out;
    float* att = out + (size_t)BATCH * CH * NPIX;

    static const size_t O6_SMEM_BYTES = (size_t)4 * STG_F * sizeof(float); // 204800
    cudaFuncSetAttribute(o_gemm6, cudaFuncAttributeMaxDynamicSharedMemorySize,
                         (int)O6_SMEM_BYTES);

    pack_w<<<320, 256>>>(Wq, bq, Wk, bk, Wv, bv);
    proj_gemm_tc<<<dim3(NPIX / 128, OCH / 64, BATCH), 256>>>(x);
    s_gemm_e<<<dim3(NPIX / 128, NPIX / 128, BATCH), 256>>>(att);
    o_gemm6<<<dim3(NPIX / 128, 1, BATCH), 512, O6_SMEM_BYTES>>>(x, gamma, att, out);
}